// round 7
// baseline (speedup 1.0000x reference)
#include <cuda_runtime.h>
#include <cstdint>

#define BATCH 64
#define S_LEN 2048
#define HID   256
#define NGEMM 84                 // GEMM-role CTAs
#define NBLK  32                 // s-blocks of 64 steps
#define NTILES 8192              // 2048 m-tiles x 4 h-tiles

// readiness counters: g_cnt[b][sb] == 4  <=>  xW[b, sb*64 .. sb*64+64) ready
__device__ int g_cnt[BATCH][NBLK];

// ---------------------------------------------------------------------------
// helpers
// ---------------------------------------------------------------------------
__device__ __forceinline__ unsigned long long fma2(unsigned long long a,
                                                   unsigned long long b,
                                                   unsigned long long c) {
    unsigned long long d;
    asm("fma.rn.f32x2 %0, %1, %2, %3;" : "=l"(d) : "l"(a), "l"(b), "l"(c));
    return d;
}
__device__ __forceinline__ unsigned long long add2(unsigned long long a,
                                                   unsigned long long b) {
    unsigned long long d;
    asm("add.rn.f32x2 %0, %1, %2;" : "=l"(d) : "l"(a), "l"(b));
    return d;
}
__device__ __forceinline__ unsigned long long pack2(float x, float y) {
    unsigned long long r;
    asm("mov.b64 %0, {%1, %2};" : "=l"(r) : "f"(x), "f"(y));
    return r;
}
__device__ __forceinline__ float2 unpack2(unsigned long long v) {
    float2 r;
    asm("mov.b64 {%0, %1}, %2;" : "=f"(r.x), "=f"(r.y) : "l"(v));
    return r;
}
__device__ __forceinline__ float tanh_fast(float x) {
    float xc = fminf(fmaxf(x, -15.0f), 15.0f);
    float ex;
    asm("ex2.approx.f32 %0, %1;" : "=f"(ex) : "f"(xc * 2.8853900817779268f));
    float rc;
    asm("rcp.approx.f32 %0, %1;" : "=f"(rc) : "f"(ex + 1.0f));
    return (ex - 1.0f) * rc;
}
__device__ __forceinline__ int ld_acq_gpu(const int* p) {
    int v;
    asm volatile("ld.acquire.gpu.b32 %0, [%1];" : "=r"(v) : "l"(p) : "memory");
    return v;
}
__device__ __forceinline__ void red_rel_gpu(int* p, int v) {
    asm volatile("red.release.gpu.global.add.s32 [%0], %1;"
                 :: "l"(p), "r"(v) : "memory");
}

// ---------------------------------------------------------------------------
// init: zero readiness counters (runs before fused kernel, every launch)
// ---------------------------------------------------------------------------
__global__ void init_cnt_kernel() {
    int i = threadIdx.x + blockIdx.x * blockDim.x;
    if (i < BATCH * NBLK) ((int*)g_cnt)[i] = 0;
}

// ---------------------------------------------------------------------------
// GEMM role: one 64m x 64h x 256k fp32 tile of xW = X @ W_ih^T
// ---------------------------------------------------------------------------
__device__ void gemm_tile(const float* __restrict__ X,
                          const float* __restrict__ Wih,
                          float* __restrict__ out,
                          int m0, int h0, char* dynsmem) {
    float (*Xs)[68] = (float (*)[68])dynsmem;
    float (*Ws)[68] = (float (*)[68])(dynsmem + 32 * 68 * sizeof(float));

    const int tid = threadIdx.x;
    const int row = tid >> 2;
    const int c4  = tid & 3;
    const int tx  = tid & 15;
    const int ty  = tid >> 4;

    unsigned long long acc[4][2];
#pragma unroll
    for (int i = 0; i < 4; i++) { acc[i][0] = 0ull; acc[i][1] = 0ull; }

    const float* Xbase = X   + (size_t)(m0 + row) * 256;
    const float* Wbase = Wih + (size_t)(h0 + row) * 256;

    float4 xa = *(const float4*)(Xbase + 0  + c4 * 4);
    float4 xb = *(const float4*)(Xbase + 16 + c4 * 4);
    float4 wa = *(const float4*)(Wbase + 0  + c4 * 4);
    float4 wb = *(const float4*)(Wbase + 16 + c4 * 4);

#pragma unroll 1
    for (int k0 = 0; k0 < 256; k0 += 32) {
        __syncthreads();
#pragma unroll
        for (int e = 0; e < 4; e++) {
            Xs[c4 * 4 + e][row]      = (&xa.x)[e];
            Xs[16 + c4 * 4 + e][row] = (&xb.x)[e];
            Ws[c4 * 4 + e][row]      = (&wa.x)[e];
            Ws[16 + c4 * 4 + e][row] = (&wb.x)[e];
        }
        float4 nxa = make_float4(0, 0, 0, 0), nxb = nxa, nwa = nxa, nwb = nxa;
        if (k0 < 224) {
            nxa = *(const float4*)(Xbase + k0 + 32 + c4 * 4);
            nxb = *(const float4*)(Xbase + k0 + 48 + c4 * 4);
            nwa = *(const float4*)(Wbase + k0 + 32 + c4 * 4);
            nwb = *(const float4*)(Wbase + k0 + 48 + c4 * 4);
        }
        __syncthreads();

#pragma unroll
        for (int kk = 0; kk < 32; kk++) {
            float4 a4 = *(const float4*)(&Xs[kk][ty * 4]);
            const unsigned long long* bp =
                (const unsigned long long*)(&Ws[kk][tx * 4]);
            unsigned long long b0 = bp[0];
            unsigned long long b1 = bp[1];
            unsigned long long aa;
            aa = pack2(a4.x, a4.x);
            acc[0][0] = fma2(aa, b0, acc[0][0]); acc[0][1] = fma2(aa, b1, acc[0][1]);
            aa = pack2(a4.y, a4.y);
            acc[1][0] = fma2(aa, b0, acc[1][0]); acc[1][1] = fma2(aa, b1, acc[1][1]);
            aa = pack2(a4.z, a4.z);
            acc[2][0] = fma2(aa, b0, acc[2][0]); acc[2][1] = fma2(aa, b1, acc[2][1]);
            aa = pack2(a4.w, a4.w);
            acc[3][0] = fma2(aa, b0, acc[3][0]); acc[3][1] = fma2(aa, b1, acc[3][1]);
        }
        xa = nxa; xb = nxb; wa = nwa; wb = nwb;
    }

#pragma unroll
    for (int i = 0; i < 4; i++) {
        float2 p = unpack2(acc[i][0]);
        float2 q = unpack2(acc[i][1]);
        float4 v = make_float4(p.x, p.y, q.x, q.y);
        *(float4*)(out + (size_t)(m0 + ty * 4 + i) * 256 + h0 + tx * 4) = v;
    }
}

__device__ void gemm_role(const float* __restrict__ X,
                          const float* __restrict__ Wih,
                          float* __restrict__ out,
                          int g, char* dynsmem) {
    // s-block-major tile order: tile = sb*256 + b*4 + h
#pragma unroll 1
    for (int tile = g; tile < NTILES; tile += NGEMM) {
        const int sb = tile >> 8;
        const int r  = tile & 255;
        const int bb = r >> 2;
        const int hh = r & 3;
        gemm_tile(X, Wih, out, bb * S_LEN + sb * 64, hh * 64, dynsmem);
        __syncthreads();                       // all tile STGs done CTA-wide
        if (threadIdx.x == 0) red_rel_gpu(&g_cnt[bb][sb], 1);
    }
}

// ---------------------------------------------------------------------------
// Scan role (v6 structure): pair-in-warp k-split, shfl combine, one barrier
// per step; consumes xW block-by-block, gated on readiness counters.
// ---------------------------------------------------------------------------
__device__ void scan_role(const float* __restrict__ Whh,
                          float* __restrict__ io, float* __restrict__ hn,
                          int b, char* dynsmem) {
    ulonglong2* Wt = (ulonglong2*)dynsmem;        // [16][256]
    __shared__ alignas(16) float hbuf[2][264];    // padded: k -> k + 4*(k>>7)

    const int t = threadIdx.x;
    const int half = t & 1;
    const int o0 = t & ~1;
    const int o1 = t | 1;
    const int hidx = t + 4 * (t >> 7);

    unsigned long long w[96];
    {
        const float4* r0 = (const float4*)(Whh + (size_t)o0 * 256 + half * 128);
        const float4* r1 = (const float4*)(Whh + (size_t)o1 * 256 + half * 128);
#pragma unroll
        for (int j = 0; j < 24; j++) {
            float4 f = r0[j];
            w[2 * j]     = pack2(f.x, f.y);
            w[2 * j + 1] = pack2(f.z, f.w);
        }
#pragma unroll
        for (int j = 0; j < 24; j++) {
            float4 f = r1[j];
            w[48 + 2 * j]     = pack2(f.x, f.y);
            w[48 + 2 * j + 1] = pack2(f.z, f.w);
        }
#pragma unroll
        for (int q = 0; q < 8; q++) {
            float4 f = r0[24 + q];
            ulonglong2 u; u.x = pack2(f.x, f.y); u.y = pack2(f.z, f.w);
            Wt[q * 256 + t] = u;
        }
#pragma unroll
        for (int q = 0; q < 8; q++) {
            float4 f = r1[24 + q];
            ulonglong2 u; u.x = pack2(f.x, f.y); u.y = pack2(f.z, f.w);
            Wt[(8 + q) * 256 + t] = u;
        }
    }

    hbuf[0][hidx] = 0.0f;
    __syncthreads();

    float* xcol = io + (size_t)b * S_LEN * HID + t;
    float xw0 = 0.0f, xw1 = 0.0f;
    float v = 0.0f;

#pragma unroll 1
    for (int sb = 0; sb < NBLK; sb++) {
        // gate: blocks sb (execution) and sb+1 (s+2 prefetch) must be ready
        if (t == 0) {
            while (ld_acq_gpu(&g_cnt[b][sb]) < 4) { }
            const int sb2 = (sb + 1 < NBLK) ? sb + 1 : NBLK - 1;
            while (ld_acq_gpu(&g_cnt[b][sb2]) < 4) { }
        }
        __syncthreads();
        if (sb == 0) { xw0 = xcol[0]; xw1 = xcol[HID]; }

#pragma unroll 1
        for (int s = sb * 64; s < sb * 64 + 64; s++) {
            const ulonglong2* h2 = (const ulonglong2*)hbuf[s & 1] + half * 33;

            unsigned long long a0 = 0ull, a1 = 0ull, b0 = 0ull, b1 = 0ull;
#pragma unroll
            for (int j = 0; j < 24; j++) {
                ulonglong2 hv = h2[j];
                a0 = fma2(w[2 * j],          hv.x, a0);
                a1 = fma2(w[2 * j + 1],      hv.y, a1);
                b0 = fma2(w[48 + 2 * j],     hv.x, b0);
                b1 = fma2(w[48 + 2 * j + 1], hv.y, b1);
            }
#pragma unroll
            for (int q = 0; q < 8; q++) {
                ulonglong2 hv = h2[24 + q];
                ulonglong2 wa = Wt[q * 256 + t];
                ulonglong2 wb = Wt[(8 + q) * 256 + t];
                a0 = fma2(wa.x, hv.x, a0);
                a1 = fma2(wa.y, hv.y, a1);
                b0 = fma2(wb.x, hv.x, b0);
                b1 = fma2(wb.y, hv.y, b1);
            }
            a0 = add2(a0, a1);
            b0 = add2(b0, b1);
            float2 pa2 = unpack2(a0);
            float2 pb2 = unpack2(b0);
            float pa = pa2.x + pa2.y;
            float pb = pb2.x + pb2.y;

            float ra = __shfl_xor_sync(0xffffffffu, pa, 1);
            float rb = __shfl_xor_sync(0xffffffffu, pb, 1);
            float total = half ? (pb + rb) : (pa + ra);

            v = tanh_fast(total + xw0);

            hbuf[(s + 1) & 1][hidx] = v;
            xcol[(size_t)s * HID] = v;

            xw0 = xw1;
            xw1 = (s + 2 < S_LEN) ? xcol[(size_t)(s + 2) * HID] : 0.0f;

            __syncthreads();
        }
    }

    hn[(size_t)b * HID + t] = v;
}

// ---------------------------------------------------------------------------
// Fused kernel: CTAs 0..63 scan (one per batch), CTAs 64..147 stream the GEMM
// ---------------------------------------------------------------------------
__global__ void __launch_bounds__(256, 1)
fused_rnn(const float* __restrict__ X, const float* __restrict__ Wih,
          const float* __restrict__ Whh, float* __restrict__ io,
          float* __restrict__ hn) {
    extern __shared__ char dynsmem[];
    if (blockIdx.x < BATCH) {
        scan_role(Whh, io, hn, blockIdx.x, dynsmem);
    } else {
        gemm_role(X, Wih, io, blockIdx.x - BATCH, dynsmem);
    }
}

// ---------------------------------------------------------------------------
extern "C" void kernel_launch(void* const* d_in, const int* in_sizes, int n_in,
                              void* d_out, int out_size) {
    (void)in_sizes; (void)n_in; (void)out_size;
    const float* x   = (const float*)d_in[0];  // [64, 2048, 256]
    const float* wih = (const float*)d_in[1];  // [256, 256]
    const float* whh = (const float*)d_in[2];  // [256, 256]
    float* out = (float*)d_out;                           // output [64,2048,256]
    float* hn  = out + (size_t)BATCH * S_LEN * HID;       // h_n [1,64,256]

    init_cnt_kernel<<<8, 256>>>();

    const int smem_bytes = 16 * 256 * (int)sizeof(ulonglong2);  // 64 KB
    cudaFuncSetAttribute(fused_rnn,
                         cudaFuncAttributeMaxDynamicSharedMemorySize,
                         smem_bytes);
    fused_rnn<<<BATCH + NGEMM, 256, smem_bytes>>>(x, wih, whh, out, hn);
}

// round 8
// speedup vs baseline: 1.0212x; 1.0212x over previous
#include <cuda_runtime.h>
#include <cstdint>

#define BATCH 64
#define S_LEN 2048
#define HID   256
#define NGEMM 84                 // GEMM-role CTAs
#define NBLK  32                 // s-blocks of 64 steps
#define NTILES 8192              // 2048 m-tiles x 4 h-tiles

// readiness counters: g_cnt[b][sb] == 4  <=>  xW[b, sb*64 .. sb*64+64) ready
__device__ int g_cnt[BATCH][NBLK];

// ---------------------------------------------------------------------------
// helpers
// ---------------------------------------------------------------------------
__device__ __forceinline__ unsigned long long fma2(unsigned long long a,
                                                   unsigned long long b,
                                                   unsigned long long c) {
    unsigned long long d;
    asm("fma.rn.f32x2 %0, %1, %2, %3;" : "=l"(d) : "l"(a), "l"(b), "l"(c));
    return d;
}
__device__ __forceinline__ unsigned long long add2(unsigned long long a,
                                                   unsigned long long b) {
    unsigned long long d;
    asm("add.rn.f32x2 %0, %1, %2;" : "=l"(d) : "l"(a), "l"(b));
    return d;
}
__device__ __forceinline__ unsigned long long pack2(float x, float y) {
    unsigned long long r;
    asm("mov.b64 %0, {%1, %2};" : "=l"(r) : "f"(x), "f"(y));
    return r;
}
__device__ __forceinline__ float2 unpack2(unsigned long long v) {
    float2 r;
    asm("mov.b64 {%0, %1}, %2;" : "=f"(r.x), "=f"(r.y) : "l"(v));
    return r;
}
__device__ __forceinline__ float tanh_fast(float x) {
    float xc = fminf(fmaxf(x, -15.0f), 15.0f);
    float ex;
    asm("ex2.approx.f32 %0, %1;" : "=f"(ex) : "f"(xc * 2.8853900817779268f));
    float rc;
    asm("rcp.approx.f32 %0, %1;" : "=f"(rc) : "f"(ex + 1.0f));
    return (ex - 1.0f) * rc;
}
__device__ __forceinline__ int ld_acq_gpu(const int* p) {
    int v;
    asm volatile("ld.acquire.gpu.b32 %0, [%1];" : "=r"(v) : "l"(p) : "memory");
    return v;
}
__device__ __forceinline__ void red_rel_gpu(int* p, int v) {
    asm volatile("red.release.gpu.global.add.s32 [%0], %1;"
                 :: "l"(p), "r"(v) : "memory");
}

// ---------------------------------------------------------------------------
// init: zero readiness counters (runs before fused kernel, every launch)
// ---------------------------------------------------------------------------
__global__ void init_cnt_kernel() {
    int i = threadIdx.x + blockIdx.x * blockDim.x;
    if (i < BATCH * NBLK) ((int*)g_cnt)[i] = 0;
}

// ---------------------------------------------------------------------------
// GEMM role: one 64m x 64h x 256k fp32 tile of xW = X @ W_ih^T
// ---------------------------------------------------------------------------
__device__ void gemm_tile(const float* __restrict__ X,
                          const float* __restrict__ Wih,
                          float* __restrict__ out,
                          int m0, int h0, char* dynsmem) {
    float (*Xs)[68] = (float (*)[68])dynsmem;
    float (*Ws)[68] = (float (*)[68])(dynsmem + 32 * 68 * sizeof(float));

    const int tid = threadIdx.x;
    const int row = tid >> 2;
    const int c4  = tid & 3;
    const int tx  = tid & 15;
    const int ty  = tid >> 4;

    unsigned long long acc[4][2];
#pragma unroll
    for (int i = 0; i < 4; i++) { acc[i][0] = 0ull; acc[i][1] = 0ull; }

    const float* Xbase = X   + (size_t)(m0 + row) * 256;
    const float* Wbase = Wih + (size_t)(h0 + row) * 256;

    float4 xa = *(const float4*)(Xbase + 0  + c4 * 4);
    float4 xb = *(const float4*)(Xbase + 16 + c4 * 4);
    float4 wa = *(const float4*)(Wbase + 0  + c4 * 4);
    float4 wb = *(const float4*)(Wbase + 16 + c4 * 4);

#pragma unroll 1
    for (int k0 = 0; k0 < 256; k0 += 32) {
        __syncthreads();
#pragma unroll
        for (int e = 0; e < 4; e++) {
            Xs[c4 * 4 + e][row]      = (&xa.x)[e];
            Xs[16 + c4 * 4 + e][row] = (&xb.x)[e];
            Ws[c4 * 4 + e][row]      = (&wa.x)[e];
            Ws[16 + c4 * 4 + e][row] = (&wb.x)[e];
        }
        float4 nxa = make_float4(0, 0, 0, 0), nxb = nxa, nwa = nxa, nwb = nxa;
        if (k0 < 224) {
            nxa = *(const float4*)(Xbase + k0 + 32 + c4 * 4);
            nxb = *(const float4*)(Xbase + k0 + 48 + c4 * 4);
            nwa = *(const float4*)(Wbase + k0 + 32 + c4 * 4);
            nwb = *(const float4*)(Wbase + k0 + 48 + c4 * 4);
        }
        __syncthreads();

#pragma unroll
        for (int kk = 0; kk < 32; kk++) {
            float4 a4 = *(const float4*)(&Xs[kk][ty * 4]);
            const unsigned long long* bp =
                (const unsigned long long*)(&Ws[kk][tx * 4]);
            unsigned long long b0 = bp[0];
            unsigned long long b1 = bp[1];
            unsigned long long aa;
            aa = pack2(a4.x, a4.x);
            acc[0][0] = fma2(aa, b0, acc[0][0]); acc[0][1] = fma2(aa, b1, acc[0][1]);
            aa = pack2(a4.y, a4.y);
            acc[1][0] = fma2(aa, b0, acc[1][0]); acc[1][1] = fma2(aa, b1, acc[1][1]);
            aa = pack2(a4.z, a4.z);
            acc[2][0] = fma2(aa, b0, acc[2][0]); acc[2][1] = fma2(aa, b1, acc[2][1]);
            aa = pack2(a4.w, a4.w);
            acc[3][0] = fma2(aa, b0, acc[3][0]); acc[3][1] = fma2(aa, b1, acc[3][1]);
        }
        xa = nxa; xb = nxb; wa = nwa; wb = nwb;
    }

#pragma unroll
    for (int i = 0; i < 4; i++) {
        float2 p = unpack2(acc[i][0]);
        float2 q = unpack2(acc[i][1]);
        float4 v = make_float4(p.x, p.y, q.x, q.y);
        *(float4*)(out + (size_t)(m0 + ty * 4 + i) * 256 + h0 + tx * 4) = v;
    }
}

__device__ void gemm_role(const float* __restrict__ X,
                          const float* __restrict__ Wih,
                          float* __restrict__ out,
                          int g, char* dynsmem) {
    // s-block-major tile order: tile = sb*256 + b*4 + h
#pragma unroll 1
    for (int tile = g; tile < NTILES; tile += NGEMM) {
        const int sb = tile >> 8;
        const int r  = tile & 255;
        const int bb = r >> 2;
        const int hh = r & 3;
        gemm_tile(X, Wih, out, bb * S_LEN + sb * 64, hh * 64, dynsmem);
        __syncthreads();                       // all tile STGs done CTA-wide
        if (threadIdx.x == 0) red_rel_gpu(&g_cnt[bb][sb], 1);
    }
}

// ---------------------------------------------------------------------------
// Scan role (v8): pair-in-warp k-split, shfl combine, one barrier per step.
// W split rebalanced to avoid spills in the fused kernel:
//   44 reg-pairs (88 floats) + 20 smem-pairs (10 ulonglong2) per output
//   -> 176 W regs (was 192), total demand ~240 < 255.
// ---------------------------------------------------------------------------
__device__ void scan_role(const float* __restrict__ Whh,
                          float* __restrict__ io, float* __restrict__ hn,
                          int b, char* dynsmem) {
    ulonglong2* Wt = (ulonglong2*)dynsmem;        // [20][256]: q<10 -> o0, q>=10 -> o1
    __shared__ alignas(16) float hbuf[2][264];    // padded: k -> k + 4*(k>>7)

    const int t = threadIdx.x;
    const int half = t & 1;
    const int hidx = t + 4 * (t >> 7);

    unsigned long long w[88];
    {
        const int o0 = t & ~1;
        const int o1 = t | 1;
        const float4* r0 = (const float4*)(Whh + (size_t)o0 * 256 + half * 128);
        const float4* r1 = (const float4*)(Whh + (size_t)o1 * 256 + half * 128);
#pragma unroll
        for (int j = 0; j < 22; j++) {
            float4 f = r0[j];
            w[2 * j]     = pack2(f.x, f.y);
            w[2 * j + 1] = pack2(f.z, f.w);
        }
#pragma unroll
        for (int j = 0; j < 22; j++) {
            float4 f = r1[j];
            w[44 + 2 * j]     = pack2(f.x, f.y);
            w[44 + 2 * j + 1] = pack2(f.z, f.w);
        }
#pragma unroll
        for (int q = 0; q < 10; q++) {
            float4 f = r0[22 + q];
            ulonglong2 u; u.x = pack2(f.x, f.y); u.y = pack2(f.z, f.w);
            Wt[q * 256 + t] = u;
        }
#pragma unroll
        for (int q = 0; q < 10; q++) {
            float4 f = r1[22 + q];
            ulonglong2 u; u.x = pack2(f.x, f.y); u.y = pack2(f.z, f.w);
            Wt[(10 + q) * 256 + t] = u;
        }
    }

    hbuf[0][hidx] = 0.0f;
    __syncthreads();

    float* xcol = io + (size_t)b * S_LEN * HID + t;
    float xw0 = 0.0f, xw1 = 0.0f;
    float v = 0.0f;

#pragma unroll 1
    for (int sb = 0; sb < NBLK; sb++) {
        // gate: blocks sb (execution) and sb+1 (s+2 prefetch) must be ready
        if (t == 0) {
            while (ld_acq_gpu(&g_cnt[b][sb]) < 4) { }
            const int sb2 = (sb + 1 < NBLK) ? sb + 1 : NBLK - 1;
            while (ld_acq_gpu(&g_cnt[b][sb2]) < 4) { }
        }
        __syncthreads();
        if (sb == 0) { xw0 = xcol[0]; xw1 = xcol[HID]; }

#pragma unroll 1
        for (int s = sb * 64; s < sb * 64 + 64; s++) {
            const ulonglong2* h2 = (const ulonglong2*)hbuf[s & 1] + half * 33;

            unsigned long long a0 = 0ull, a1 = 0ull, b0 = 0ull, b1 = 0ull;
#pragma unroll
            for (int j = 0; j < 22; j++) {          // reg W: k-pairs 0..43
                ulonglong2 hv = h2[j];
                a0 = fma2(w[2 * j],          hv.x, a0);
                a1 = fma2(w[2 * j + 1],      hv.y, a1);
                b0 = fma2(w[44 + 2 * j],     hv.x, b0);
                b1 = fma2(w[44 + 2 * j + 1], hv.y, b1);
            }
#pragma unroll
            for (int q = 0; q < 10; q++) {          // smem W: k-pairs 44..63
                ulonglong2 hv = h2[22 + q];
                ulonglong2 wa = Wt[q * 256 + t];
                ulonglong2 wb = Wt[(10 + q) * 256 + t];
                a0 = fma2(wa.x, hv.x, a0);
                a1 = fma2(wa.y, hv.y, a1);
                b0 = fma2(wb.x, hv.x, b0);
                b1 = fma2(wb.y, hv.y, b1);
            }
            a0 = add2(a0, a1);
            b0 = add2(b0, b1);
            float2 pa2 = unpack2(a0);
            float2 pb2 = unpack2(b0);
            float pa = pa2.x + pa2.y;
            float pb = pb2.x + pb2.y;

            float ra = __shfl_xor_sync(0xffffffffu, pa, 1);
            float rb = __shfl_xor_sync(0xffffffffu, pb, 1);
            float total = half ? (pb + rb) : (pa + ra);

            v = tanh_fast(total + xw0);

            hbuf[(s + 1) & 1][hidx] = v;
            xcol[(size_t)s * HID] = v;

            xw0 = xw1;
            const int sp = (s + 2 < S_LEN) ? s + 2 : S_LEN - 1;
            xw1 = xcol[(size_t)sp * HID];

            __syncthreads();
        }
    }

    hn[(size_t)b * HID + t] = v;
}

// ---------------------------------------------------------------------------
// Fused kernel: CTAs 0..63 scan (one per batch), CTAs 64..147 stream the GEMM
// ---------------------------------------------------------------------------
__global__ void __launch_bounds__(256, 1)
fused_rnn(const float* __restrict__ X, const float* __restrict__ Wih,
          const float* __restrict__ Whh, float* __restrict__ io,
          float* __restrict__ hn) {
    extern __shared__ char dynsmem[];
    if (blockIdx.x < BATCH) {
        scan_role(Whh, io, hn, blockIdx.x, dynsmem);
    } else {
        gemm_role(X, Wih, io, blockIdx.x - BATCH, dynsmem);
    }
}

// ---------------------------------------------------------------------------
extern "C" void kernel_launch(void* const* d_in, const int* in_sizes, int n_in,
                              void* d_out, int out_size) {
    (void)in_sizes; (void)n_in; (void)out_size;
    const float* x   = (const float*)d_in[0];  // [64, 2048, 256]
    const float* wih = (const float*)d_in[1];  // [256, 256]
    const float* whh = (const float*)d_in[2];  // [256, 256]
    float* out = (float*)d_out;                           // output [64,2048,256]
    float* hn  = out + (size_t)BATCH * S_LEN * HID;       // h_n [1,64,256]

    init_cnt_kernel<<<8, 256>>>();

    const int smem_bytes = 20 * 256 * (int)sizeof(ulonglong2);  // 80 KB
    cudaFuncSetAttribute(fused_rnn,
                         cudaFuncAttributeMaxDynamicSharedMemorySize,
                         smem_bytes);
    fused_rnn<<<BATCH + NGEMM, 256, smem_bytes>>>(x, wih, whh, out, hn);
}